// round 11
// baseline (speedup 1.0000x reference)
#include <cuda_runtime.h>
#include <cuda_fp16.h>
#include <cuda_fp8.h>
#include <math.h>

#define BB 8
#define NN 2048
#define DD 128
#define TWO_PI_F 6.283185307179586f

// Static device scratch (no allocations allowed).
__device__ unsigned char d_C8[(size_t)BB * NN * NN];  // coupling e4m3, normal layout (full, via mirror)
__device__ unsigned char d_Cf[(size_t)BB * NN * NN];  // coupling e4m3 in m16n8k32 A-fragment layout
__device__ unsigned char d_cos8[2][BB * NN];          // ping-pong fp8 cos(theta)
__device__ unsigned char d_sin8[2][BB * NN];          // ping-pong fp8 sin(theta)
__device__ unsigned long long d_barA;                 // step barrier (monotonic, self-reset)
__device__ int d_barB;                                // exit counter for reset

// ---- packed f32x2 helpers (Blackwell FFMA2, used in build) ----
static __device__ __forceinline__ unsigned long long pack2(float lo, float hi) {
    unsigned long long r;
    asm("mov.b64 %0, {%1, %2};" : "=l"(r) : "f"(lo), "f"(hi));
    return r;
}
static __device__ __forceinline__ void unpack2(unsigned long long v, float& lo, float& hi) {
    asm("mov.b64 {%0, %1}, %2;" : "=f"(lo), "=f"(hi) : "l"(v));
}
static __device__ __forceinline__ void fma2(unsigned long long& d,
                                            unsigned long long a,
                                            unsigned long long b) {
    asm("fma.rn.f32x2 %0, %1, %2, %0;" : "+l"(d) : "l"(a), "l"(b));
}

// coupling ≈ x - sqrt(x^2-1), x = max(-lz, 1+1e-7)
__device__ __forceinline__ float coupling_from_lz(float lz) {
    float x = fmaxf(-lz, 1.0f + 1e-7f);
    float t = (x - 1.0f) * (x + 1.0f);
    float xh = 0.5f * t;
    float r = __int_as_float(0x5f375a86 - (__float_as_int(t) >> 1));
    r = r * (1.5f - xh * r * r);
    r = r * (1.5f - xh * r * r);
    r = r * (1.5f - xh * r * r);
    float s = t * r;
    float c = x - s;
    return fminf(fmaxf(c, 0.0f), 1.0f);
}

static __device__ __forceinline__ unsigned fp8x4_from_floats(float c0, float c1,
                                                             float c2, float c3) {
    __nv_fp8x2_storage_t p01 =
        __nv_cvt_float2_to_fp8x2(make_float2(c0, c1), __NV_SATFINITE, __NV_E4M3);
    __nv_fp8x2_storage_t p23 =
        __nv_cvt_float2_to_fp8x2(make_float2(c2, c3), __NV_SATFINITE, __NV_E4M3);
    return (unsigned)p01 | ((unsigned)p23 << 16);
}

#define BM 64
#define BN 64
#define BK 32

// Build C for upper-triangle 128-tiles; strictly-upper blocks also write the
// transposed mirror (normal layout ends up FULL symmetric).
__global__ void build_coupling_kernel(const float* __restrict__ emb) {
    int m128 = blockIdx.x >> 1;
    int n128 = blockIdx.y >> 1;
    if (m128 < n128) return;
    bool twrite = (m128 > n128);

    int b  = blockIdx.z;
    int n0 = blockIdx.y * BM;
    int m0 = blockIdx.x * BN;
    const float* E = emb + (size_t)b * NN * DD;

    __shared__ __align__(16) float As[BK][BM];
    __shared__ __align__(16) float Bs[BK][BN];
    __shared__ unsigned shT[64 * 17];

    int tx = threadIdx.x, ty = threadIdx.y;    // block (16,16)
    int tid = ty * 16 + tx;
    int loadRow = tid >> 3;
    int loadK   = (tid & 7) * 4;

    unsigned long long acc[4][2] = {};

    for (int k0 = 0; k0 < DD; k0 += BK) {
        #pragma unroll
        for (int rr = 0; rr < 2; rr++) {
            int row = loadRow + rr * 32;
            float4 v = *(const float4*)(E + (size_t)(n0 + row) * DD + k0 + loadK);
            if (k0 == 0 && loadK == 0) v.x = -v.x;
            As[loadK + 0][row] = v.x;
            As[loadK + 1][row] = v.y;
            As[loadK + 2][row] = v.z;
            As[loadK + 3][row] = v.w;
            float4 w = *(const float4*)(E + (size_t)(m0 + row) * DD + k0 + loadK);
            Bs[loadK + 0][row] = w.x;
            Bs[loadK + 1][row] = w.y;
            Bs[loadK + 2][row] = w.z;
            Bs[loadK + 3][row] = w.w;
        }
        __syncthreads();

        #pragma unroll
        for (int kk = 0; kk < BK; kk++) {
            float4 a4 = *(const float4*)&As[kk][ty * 4];
            ulonglong2 b2 = *(const ulonglong2*)&Bs[kk][tx * 4];
            unsigned long long a0 = pack2(a4.x, a4.x);
            unsigned long long a1 = pack2(a4.y, a4.y);
            unsigned long long a2 = pack2(a4.z, a4.z);
            unsigned long long a3 = pack2(a4.w, a4.w);
            fma2(acc[0][0], a0, b2.x); fma2(acc[0][1], a0, b2.y);
            fma2(acc[1][0], a1, b2.x); fma2(acc[1][1], a1, b2.y);
            fma2(acc[2][0], a2, b2.x); fma2(acc[2][1], a2, b2.y);
            fma2(acc[3][0], a3, b2.x); fma2(acc[3][1], a3, b2.y);
        }
        __syncthreads();
    }

    #pragma unroll
    for (int i = 0; i < 4; i++) {
        int n = n0 + ty * 4 + i;
        float c0, c1, c2, c3;
        unpack2(acc[i][0], c0, c1);
        unpack2(acc[i][1], c2, c3);
        c0 = coupling_from_lz(c0);
        c1 = coupling_from_lz(c1);
        c2 = coupling_from_lz(c2);
        c3 = coupling_from_lz(c3);
        unsigned o = fp8x4_from_floats(c0, c1, c2, c3);
        *(unsigned*)(d_C8 + ((size_t)b * NN + n) * NN + m0 + tx * 4) = o;
        if (twrite) shT[(ty * 4 + i) * 17 + tx] = o;
    }

    if (twrite) {
        __syncthreads();
        #pragma unroll
        for (int k = 0; k < 4; k++) {
            int idx = k * 256 + tid;
            int mm = idx >> 4;
            int qn = idx & 15;
            int word = mm >> 2, sh = (mm & 3) * 8;
            unsigned u0 = shT[(qn * 4 + 0) * 17 + word];
            unsigned u1 = shT[(qn * 4 + 1) * 17 + word];
            unsigned u2 = shT[(qn * 4 + 2) * 17 + word];
            unsigned u3 = shT[(qn * 4 + 3) * 17 + word];
            unsigned o = ((u0 >> sh) & 0xFFu)
                       | (((u1 >> sh) & 0xFFu) << 8)
                       | (((u2 >> sh) & 0xFFu) << 16)
                       | (((u3 >> sh) & 0xFFu) << 24);
            *(unsigned*)(d_C8 + ((size_t)b * NN + m0 + mm) * NN + n0 + qn * 4) = o;
        }
    }
}

// Repack normal-layout fp8 C into m16n8k32 A-fragment layout.
#define RP_PITCH 144
__global__ void __launch_bounds__(256) repack_kernel() {
    __shared__ unsigned char sh[128 * RP_PITCH];
    int b = blockIdx.z, MT = blockIdx.y, KT = blockIdx.x;    // 16 x 16
    int tid = threadIdx.x;
    const unsigned char* src = d_C8 + ((size_t)b * NN + MT * 128) * NN + KT * 128;

    #pragma unroll
    for (int i = 0; i < 4; i++) {
        int idx = tid + i * 256;          // 1024 uint4 = 128 rows x 8
        int r = idx >> 3, q = idx & 7;
        uint4 v = *(const uint4*)(src + (size_t)r * NN + q * 16);
        *(uint4*)(sh + r * RP_PITCH + q * 16) = v;
    }
    __syncthreads();

    int lane = tid & 31, w = tid >> 5;
    int gid = lane >> 2, tig = lane & 3;
    #pragma unroll
    for (int s = 0; s < 4; s++) {
        int tt  = s * 8 + w;              // 0..31 local tiles
        int mtl = tt >> 2, ktl = tt & 3;  // 8 m-tiles x 4 k-slabs
        const unsigned char* base = sh + (mtl * 16 + gid) * RP_PITCH + ktl * 32 + tig * 4;
        uint4 o;
        o.x = *(const unsigned*)(base);
        o.y = *(const unsigned*)(base + 8 * RP_PITCH);
        o.z = *(const unsigned*)(base + 16);
        o.w = *(const unsigned*)(base + 8 * RP_PITCH + 16);
        size_t toff = (((size_t)(b * 128 + MT * 8 + mtl)) * 64 + KT * 4 + ktl) * 512
                    + (size_t)lane * 16;
        *(uint4*)(d_Cf + toff) = o;
    }
}

__global__ void init_trig_kernel(const float* __restrict__ th) {
    int i = blockIdx.x * 256 + threadIdx.x;
    float s, c;
    sincosf(th[i], &s, &c);
    d_cos8[0][i] = (unsigned char)__nv_cvt_float_to_fp8(c, __NV_SATFINITE, __NV_E4M3);
    d_sin8[0][i] = (unsigned char)__nv_cvt_float_to_fp8(s, __NV_SATFINITE, __NV_E4M3);
}

// PERSISTENT step kernel: ALL 16 steps in one launch. 128 blocks (<=148 SMs,
// all co-resident => safe grid barrier). Each block keeps its 128 thetas in
// registers and re-reads the SAME contiguous 256KB d_Cf slice every step
// (L1/L2-resident after step 0). Trig is fp8, double-buffered by step parity,
// read via __ldcg (L2-coherent). Barrier counters self-reset for graph replay.
__global__ void __launch_bounds__(512, 1)
steps_kernel(const float* __restrict__ th_in,
             float* __restrict__ th_out,
             const float* __restrict__ omega) {
    __shared__ unsigned shCos[512];
    __shared__ unsigned shSin[512];
    __shared__ float shPC[2][128];
    __shared__ float shPS[2][128];

    int rg = blockIdx.x, b = blockIdx.y;
    int tid = threadIdx.x;
    int w = tid >> 5, lane = tid & 31;
    int gid = lane >> 2, tig = lane & 3;
    int mtl = w & 7, kq = w >> 3;

    int mt = rg * 8 + mtl;
    const uint4* Af = (const uint4*)(d_Cf
        + (((size_t)(b * 128 + mt)) * 64 + kq * 32) * 512) + lane;
    int bbase = kq * 256 + tig;

    // register-resident oscillator state (tid < 128)
    int gi = b * NN + rg * 128 + tid;
    float th = 0.f, om = 0.f;
    if (tid < 128) { th = th_in[gi]; om = omega[rg * 128 + tid]; }

    for (int k = 0; k < 16; k++) {
        if (k > 0) {
            if (tid == 0) {
                unsigned long long target = (unsigned long long)(128 * k);
                unsigned long long v;
                for (;;) {
                    asm volatile("ld.acquire.gpu.global.u64 %0, [%1];"
                                 : "=l"(v) : "l"(&d_barA) : "memory");
                    if (v >= target) break;
                    __nanosleep(64);
                }
            }
            __syncthreads();
        }

        // stage this batch's trig (buffer k&1): 512 words cos + 512 words sin
        {
            const unsigned* gc = (const unsigned*)(d_cos8[k & 1] + (size_t)b * NN);
            const unsigned* gs = (const unsigned*)(d_sin8[k & 1] + (size_t)b * NN);
            shCos[tid] = __ldcg(gc + tid);     // .cg: L2-coherent, skip stale L1
            shSin[tid] = __ldcg(gs + tid);
        }
        __syncthreads();

        const unsigned* bp = (gid == 1) ? shSin : shCos;

        // stream slice: 32 k-slabs, rolling depth-8 register pipeline (L1-cached)
        uint4 a[8];
        #pragma unroll
        for (int i = 0; i < 8; i++) a[i] = Af[i * 32];

        float d0 = 0.f, d1 = 0.f, d2 = 0.f, d3 = 0.f;
        #pragma unroll
        for (int it = 0; it < 32; it++) {
            uint4 cur = a[it & 7];
            if (it + 8 < 32) a[it & 7] = Af[(it + 8) * 32];
            unsigned b0 = bp[bbase + it * 8];
            unsigned b1 = bp[bbase + it * 8 + 4];
            asm volatile(
                "mma.sync.aligned.m16n8k32.row.col.f32.e4m3.e4m3.f32 "
                "{%0,%1,%2,%3}, {%4,%5,%6,%7}, {%8,%9}, {%0,%1,%2,%3};"
                : "+f"(d0), "+f"(d1), "+f"(d2), "+f"(d3)
                : "r"(cur.x), "r"(cur.y), "r"(cur.z), "r"(cur.w), "r"(b0), "r"(b1));
        }

        if (tig == 0) {
            int lr = mtl * 16 + gid;
            shPC[kq][lr]     = d0;
            shPS[kq][lr]     = d1;
            shPC[kq][lr + 8] = d2;
            shPS[kq][lr + 8] = d3;
        }
        __syncthreads();

        if (tid < 128) {
            float yc = shPC[0][tid] + shPC[1][tid];   // fixed order -> deterministic
            float ys = shPS[0][tid] + shPS[1][tid];
            float sn, cn;
            sincosf(th, &sn, &cn);
            float csum = sn * yc - cn * ys;
            float dth = om + (1.0f / NN) * csum;
            th = fmodf(th + 0.1f * dth, TWO_PI_F);
            if (k < 15) {
                float s2, c2;
                sincosf(th, &s2, &c2);
                d_cos8[(k + 1) & 1][gi] =
                    (unsigned char)__nv_cvt_float_to_fp8(c2, __NV_SATFINITE, __NV_E4M3);
                d_sin8[(k + 1) & 1][gi] =
                    (unsigned char)__nv_cvt_float_to_fp8(s2, __NV_SATFINITE, __NV_E4M3);
                __threadfence();                       // release trig writes
            } else {
                th_out[gi] = th;
            }
        }
        __syncthreads();
        if (k < 15 && tid == 0) atomicAdd(&d_barA, 1ULL);
    }

    // exit: last block resets counters so every graph replay starts clean
    __syncthreads();
    if (tid == 0) {
        int old = atomicAdd(&d_barB, 1);
        if (old == 127) {
            atomicExch(&d_barA, 0ULL);
            atomicExch(&d_barB, 0);
        }
    }
}

extern "C" void kernel_launch(void* const* d_in, const int* in_sizes, int n_in,
                              void* d_out, int out_size) {
    const float* initial = (const float*)d_in[0];   // (B,N)
    const float* emb     = (const float*)d_in[1];   // (B,N,D)
    const float* omega   = (const float*)d_in[2];   // (N,)
    float* out = (float*)d_out;                     // (B,N)

    dim3 bgrid(NN / BN, NN / BM, BB);
    dim3 bblock(16, 16);
    build_coupling_kernel<<<bgrid, bblock>>>(emb);

    dim3 rgrid(16, 16, BB);
    repack_kernel<<<rgrid, 256>>>();

    init_trig_kernel<<<BB * NN / 256, 256>>>(initial);

    dim3 sgrid(16, BB);                             // 128 blocks, all co-resident
    steps_kernel<<<sgrid, 512>>>(initial, out, omega);
}

// round 12
// speedup vs baseline: 1.5637x; 1.5637x over previous
#include <cuda_runtime.h>
#include <cuda_fp16.h>
#include <cuda_fp8.h>
#include <math.h>

#define BB 8
#define NN 2048
#define DD 128
#define TWO_PI_F 6.283185307179586f

// Static device scratch (no allocations allowed).
__device__ unsigned char d_C8[(size_t)BB * NN * NN];  // coupling e4m3, normal layout (full, via mirror)
__device__ unsigned char d_Cf[(size_t)BB * NN * NN];  // coupling e4m3 in m16n8k32 A-fragment layout
__device__ unsigned char d_cos8[2][BB * NN];          // ping-pong fp8 cos(theta)
__device__ unsigned char d_sin8[2][BB * NN];          // ping-pong fp8 sin(theta)
__device__ unsigned d_barStep[BB];                    // per-batch step barriers (BSS=0)
__device__ int d_barExit;                             // exit counter for reset

// coupling ≈ x - sqrt(x^2-1), x = max(-lz, 1+1e-7)
__device__ __forceinline__ float coupling_from_lz(float lz) {
    float x = fmaxf(-lz, 1.0f + 1e-7f);
    float t = (x - 1.0f) * (x + 1.0f);
    float xh = 0.5f * t;
    float r = __int_as_float(0x5f375a86 - (__float_as_int(t) >> 1));
    r = r * (1.5f - xh * r * r);
    r = r * (1.5f - xh * r * r);
    r = r * (1.5f - xh * r * r);
    float s = t * r;
    float c = x - s;
    return fminf(fmaxf(c, 0.0f), 1.0f);
}

static __device__ __forceinline__ float to_tf32(float x) {
    unsigned u;
    asm("cvt.rna.tf32.f32 %0, %1;" : "=r"(u) : "f"(x));
    return __uint_as_float(u);
}

#define AP 132            // smem pitch (floats), conflict-free fragment LDS
#define SP 144            // fp8 stage pitch (bytes), 16B-aligned rows
#define BUILD_SMEM (2 * 128 * AP * 4)

// tf32 tensor-core build: one block = one 128x128 upper-triangle tile (I,J).
// K=128 staged once (tf32-rounded). Epilogue: coupling->fp8, write tile +
// transposed mirror (both coalesced via smem stage).
__global__ void __launch_bounds__(256, 1)
build_tf32_kernel(const float* __restrict__ emb) {
    extern __shared__ float dynb[];
    float* Asm = dynb;                 // [128][AP]
    float* Bsm = dynb + 128 * AP;

    int t = blockIdx.x, I = 0;
    while (t >= 16 - I) { t -= 16 - I; I++; }
    int J = I + t;
    int b = blockIdx.y;
    bool offdiag = (J != I);

    int tid = threadIdx.x;
    int w = tid >> 5, lane = tid & 31;
    int gid = lane >> 2, tig = lane & 3;

    const float* EI = emb + ((size_t)b * NN + I * 128) * DD;
    const float* EJ = emb + ((size_t)b * NN + J * 128) * DD;

    // stage both 128x128 tiles, tf32-rounded; negate time component on A side
    #pragma unroll
    for (int i = 0; i < 16; i++) {
        int idx = tid + i * 256;
        int r = idx >> 5, q = idx & 31;
        float4 v = *(const float4*)(EI + (size_t)r * DD + q * 4);
        if (q == 0) v.x = -v.x;
        float* d = &Asm[r * AP + q * 4];
        d[0] = to_tf32(v.x); d[1] = to_tf32(v.y);
        d[2] = to_tf32(v.z); d[3] = to_tf32(v.w);
        float4 u = *(const float4*)(EJ + (size_t)r * DD + q * 4);
        float* e = &Bsm[r * AP + q * 4];
        e[0] = to_tf32(u.x); e[1] = to_tf32(u.y);
        e[2] = to_tf32(u.z); e[3] = to_tf32(u.w);
    }
    __syncthreads();

    float acc[16][4];
    #pragma unroll
    for (int nt = 0; nt < 16; nt++) {
        acc[nt][0] = 0.f; acc[nt][1] = 0.f; acc[nt][2] = 0.f; acc[nt][3] = 0.f;
    }

    int mrow = (w << 4) + gid;         // warp's m-tile rows: mrow, mrow+8
    #pragma unroll
    for (int k0 = 0; k0 < 128; k0 += 8) {
        const float* Ab = &Asm[mrow * AP + k0 + tig];
        unsigned a0 = __float_as_uint(Ab[0]);
        unsigned a1 = __float_as_uint(Ab[8 * AP]);
        unsigned a2 = __float_as_uint(Ab[4]);
        unsigned a3 = __float_as_uint(Ab[8 * AP + 4]);
        #pragma unroll
        for (int nt = 0; nt < 16; nt++) {
            const float* Bb = &Bsm[(nt * 8 + gid) * AP + k0 + tig];
            unsigned b0 = __float_as_uint(Bb[0]);
            unsigned b1 = __float_as_uint(Bb[4]);
            asm volatile(
                "mma.sync.aligned.m16n8k8.row.col.f32.tf32.tf32.f32 "
                "{%0,%1,%2,%3}, {%4,%5,%6,%7}, {%8,%9}, {%0,%1,%2,%3};"
                : "+f"(acc[nt][0]), "+f"(acc[nt][1]), "+f"(acc[nt][2]), "+f"(acc[nt][3])
                : "r"(a0), "r"(a1), "r"(a2), "r"(a3), "r"(b0), "r"(b1));
        }
    }
    __syncthreads();

    // fp8 stage (aliases Asm region)
    unsigned char* stg = (unsigned char*)dynb;
    #pragma unroll
    for (int nt = 0; nt < 16; nt++) {
        float c0 = coupling_from_lz(acc[nt][0]);   // (mrow,   2tig)
        float c1 = coupling_from_lz(acc[nt][1]);   // (mrow,   2tig+1)
        float c2 = coupling_from_lz(acc[nt][2]);   // (mrow+8, 2tig)
        float c3 = coupling_from_lz(acc[nt][3]);   // (mrow+8, 2tig+1)
        unsigned short p01 = (unsigned short)__nv_cvt_float2_to_fp8x2(
            make_float2(c0, c1), __NV_SATFINITE, __NV_E4M3);
        unsigned short p23 = (unsigned short)__nv_cvt_float2_to_fp8x2(
            make_float2(c2, c3), __NV_SATFINITE, __NV_E4M3);
        int col = nt * 8 + tig * 2;
        *(unsigned short*)(stg + mrow * SP + col)       = p01;
        *(unsigned short*)(stg + (mrow + 8) * SP + col) = p23;
    }
    __syncthreads();

    // normal write (rows = I-block, cols = J-block), coalesced uint4
    size_t outN = ((size_t)b * NN + I * 128) * NN + J * 128;
    #pragma unroll
    for (int i = 0; i < 4; i++) {
        int idx = tid + i * 256;
        int r = idx >> 3, q = idx & 7;
        uint4 v = *(const uint4*)(stg + r * SP + q * 16);
        *(uint4*)(d_C8 + outN + (size_t)r * NN + q * 16) = v;
    }
    // transposed mirror (rows = J-block, cols = I-block)
    if (offdiag) {
        size_t outT = ((size_t)b * NN + J * 128) * NN + I * 128;
        #pragma unroll
        for (int i = 0; i < 4; i++) {
            int idx = tid + i * 256;
            int r = idx >> 3, q = idx & 7;
            unsigned wds[4];
            #pragma unroll
            for (int jj = 0; jj < 4; jj++) {
                int n0 = q * 16 + jj * 4;
                unsigned x0 = stg[(n0 + 0) * SP + r];
                unsigned x1 = stg[(n0 + 1) * SP + r];
                unsigned x2 = stg[(n0 + 2) * SP + r];
                unsigned x3 = stg[(n0 + 3) * SP + r];
                wds[jj] = x0 | (x1 << 8) | (x2 << 16) | (x3 << 24);
            }
            uint4 v = make_uint4(wds[0], wds[1], wds[2], wds[3]);
            *(uint4*)(d_C8 + outT + (size_t)r * NN + q * 16) = v;
        }
    }
}

// Repack normal-layout fp8 C into m16n8k32 A-fragment layout.
#define RP_PITCH 144
__global__ void __launch_bounds__(256) repack_kernel() {
    __shared__ unsigned char sh[128 * RP_PITCH];
    int b = blockIdx.z, MT = blockIdx.y, KT = blockIdx.x;    // 16 x 16
    int tid = threadIdx.x;
    const unsigned char* src = d_C8 + ((size_t)b * NN + MT * 128) * NN + KT * 128;

    #pragma unroll
    for (int i = 0; i < 4; i++) {
        int idx = tid + i * 256;          // 1024 uint4 = 128 rows x 8
        int r = idx >> 3, q = idx & 7;
        uint4 v = *(const uint4*)(src + (size_t)r * NN + q * 16);
        *(uint4*)(sh + r * RP_PITCH + q * 16) = v;
    }
    __syncthreads();

    int lane = tid & 31, w = tid >> 5;
    int gid = lane >> 2, tig = lane & 3;
    #pragma unroll
    for (int s = 0; s < 4; s++) {
        int tt  = s * 8 + w;              // 0..31 local tiles
        int mtl = tt >> 2, ktl = tt & 3;  // 8 m-tiles x 4 k-slabs
        const unsigned char* base = sh + (mtl * 16 + gid) * RP_PITCH + ktl * 32 + tig * 4;
        uint4 o;
        o.x = *(const unsigned*)(base);
        o.y = *(const unsigned*)(base + 8 * RP_PITCH);
        o.z = *(const unsigned*)(base + 16);
        o.w = *(const unsigned*)(base + 8 * RP_PITCH + 16);
        size_t toff = (((size_t)(b * 128 + MT * 8 + mtl)) * 64 + KT * 4 + ktl) * 512
                    + (size_t)lane * 16;
        *(uint4*)(d_Cf + toff) = o;
    }
}

__global__ void init_trig_kernel(const float* __restrict__ th) {
    int i = blockIdx.x * 256 + threadIdx.x;
    float s, c;
    sincosf(th[i], &s, &c);
    d_cos8[0][i] = (unsigned char)__nv_cvt_float_to_fp8(c, __NV_SATFINITE, __NV_E4M3);
    d_sin8[0][i] = (unsigned char)__nv_cvt_float_to_fp8(s, __NV_SATFINITE, __NV_E4M3);
}

// PERSISTENT step kernel: all 16 steps, 128 co-resident blocks.
// Per-batch barriers (16 arrivals), cross-step C-fragment prefetch (wrapping
// register pipeline), carried full-precision sincos.
__global__ void __launch_bounds__(512, 1)
steps_kernel(const float* __restrict__ th_in,
             float* __restrict__ th_out,
             const float* __restrict__ omega) {
    __shared__ unsigned shCos[512];
    __shared__ unsigned shSin[512];
    __shared__ float shPC[2][128];
    __shared__ float shPS[2][128];

    int rg = blockIdx.x, b = blockIdx.y;
    int tid = threadIdx.x;
    int w = tid >> 5, lane = tid & 31;
    int gid = lane >> 2, tig = lane & 3;
    int mtl = w & 7, kq = w >> 3;

    int mt = rg * 8 + mtl;
    const uint4* Af = (const uint4*)(d_Cf
        + (((size_t)(b * 128 + mt)) * 64 + kq * 32) * 512) + lane;
    int bbase = kq * 256 + tig;

    // register-resident oscillator state (tid < 128)
    int gi = b * NN + rg * 128 + tid;
    float th = 0.f, om = 0.f, sn = 0.f, cn = 0.f;
    if (tid < 128) {
        th = th_in[gi];
        om = omega[rg * 128 + tid];
        sincosf(th, &sn, &cn);
    }

    // C-fragment pipeline (step-invariant addresses -> wraps across steps)
    uint4 a[8];
    #pragma unroll
    for (int i = 0; i < 8; i++) a[i] = Af[i * 32];

    for (int k = 0; k < 16; k++) {
        if (k > 0) {
            if (tid == 0) {
                unsigned target = 16u * (unsigned)k;
                unsigned v;
                do {
                    asm volatile("ld.acquire.gpu.global.u32 %0, [%1];"
                                 : "=r"(v) : "l"(&d_barStep[b]) : "memory");
                } while (v < target);
            }
            __syncthreads();
        }

        // stage this batch's trig (buffer k&1)
        {
            const unsigned* gc = (const unsigned*)(d_cos8[k & 1] + (size_t)b * NN);
            const unsigned* gs = (const unsigned*)(d_sin8[k & 1] + (size_t)b * NN);
            shCos[tid] = __ldcg(gc + tid);
            shSin[tid] = __ldcg(gs + tid);
        }
        __syncthreads();

        const unsigned* bp = (gid == 1) ? shSin : shCos;

        float d0 = 0.f, d1 = 0.f, d2 = 0.f, d3 = 0.f;
        #pragma unroll
        for (int it = 0; it < 32; it++) {
            uint4 cur = a[it & 7];
            a[it & 7] = Af[((it + 8) & 31) * 32];   // wraps -> prefetch next step
            unsigned b0 = bp[bbase + it * 8];
            unsigned b1 = bp[bbase + it * 8 + 4];
            asm volatile(
                "mma.sync.aligned.m16n8k32.row.col.f32.e4m3.e4m3.f32 "
                "{%0,%1,%2,%3}, {%4,%5,%6,%7}, {%8,%9}, {%0,%1,%2,%3};"
                : "+f"(d0), "+f"(d1), "+f"(d2), "+f"(d3)
                : "r"(cur.x), "r"(cur.y), "r"(cur.z), "r"(cur.w), "r"(b0), "r"(b1));
        }

        if (tig == 0) {
            int lr = mtl * 16 + gid;
            shPC[kq][lr]     = d0;
            shPS[kq][lr]     = d1;
            shPC[kq][lr + 8] = d2;
            shPS[kq][lr + 8] = d3;
        }
        __syncthreads();

        if (tid < 128) {
            float yc = shPC[0][tid] + shPC[1][tid];   // fixed order -> deterministic
            float ys = shPS[0][tid] + shPS[1][tid];
            float csum = sn * yc - cn * ys;
            float dth = om + (1.0f / NN) * csum;
            th = fmodf(th + 0.1f * dth, TWO_PI_F);
            sincosf(th, &sn, &cn);
            if (k < 15) {
                d_cos8[(k + 1) & 1][gi] =
                    (unsigned char)__nv_cvt_float_to_fp8(cn, __NV_SATFINITE, __NV_E4M3);
                d_sin8[(k + 1) & 1][gi] =
                    (unsigned char)__nv_cvt_float_to_fp8(sn, __NV_SATFINITE, __NV_E4M3);
                __threadfence();                       // release trig writes
            } else {
                th_out[gi] = th;
            }
        }
        __syncthreads();
        if (k < 15 && tid == 0)
            asm volatile("red.release.gpu.global.add.u32 [%0], %1;"
                         :: "l"(&d_barStep[b]), "r"(1u) : "memory");
    }

    // exit: last block resets counters so every graph replay starts clean
    __syncthreads();
    if (tid == 0) {
        int old = atomicAdd(&d_barExit, 1);
        if (old == 127) {
            #pragma unroll
            for (int i = 0; i < BB; i++) atomicExch(&d_barStep[i], 0u);
            atomicExch(&d_barExit, 0);
        }
    }
}

extern "C" void kernel_launch(void* const* d_in, const int* in_sizes, int n_in,
                              void* d_out, int out_size) {
    const float* initial = (const float*)d_in[0];   // (B,N)
    const float* emb     = (const float*)d_in[1];   // (B,N,D)
    const float* omega   = (const float*)d_in[2];   // (N,)
    float* out = (float*)d_out;                     // (B,N)

    cudaFuncSetAttribute(build_tf32_kernel,
                         cudaFuncAttributeMaxDynamicSharedMemorySize, BUILD_SMEM);

    dim3 bgrid(136, BB);                            // upper-triangle 128-tiles
    build_tf32_kernel<<<bgrid, 256, BUILD_SMEM>>>(emb);

    dim3 rgrid(16, 16, BB);
    repack_kernel<<<rgrid, 256>>>();

    init_trig_kernel<<<BB * NN / 256, 256>>>(initial);

    dim3 sgrid(16, BB);                             // 128 blocks, all co-resident
    steps_kernel<<<sgrid, 512>>>(initial, out, omega);
}

// round 13
// speedup vs baseline: 1.8891x; 1.2081x over previous
#include <cuda_runtime.h>
#include <cuda_fp16.h>
#include <cuda_fp8.h>
#include <math.h>

#define BB 8
#define NN 2048
#define DD 128
#define TWO_PI_F 6.283185307179586f

// Static device scratch (no allocations allowed).
__device__ unsigned char d_Cf[(size_t)BB * NN * NN];  // coupling e4m3, m16n8k32 A-fragment layout
__device__ unsigned char d_cos8[2][BB * NN];          // ping-pong fp8 cos(theta)
__device__ unsigned char d_sin8[2][BB * NN];          // ping-pong fp8 sin(theta)
__device__ unsigned d_barStep[BB];                    // per-batch step barriers (BSS=0)
__device__ int d_barExit;                             // exit counter for reset

// coupling ≈ x - sqrt(x^2-1), x = max(-lz, 1+1e-7)
__device__ __forceinline__ float coupling_from_lz(float lz) {
    float x = fmaxf(-lz, 1.0f + 1e-7f);
    float t = (x - 1.0f) * (x + 1.0f);
    float xh = 0.5f * t;
    float r = __int_as_float(0x5f375a86 - (__float_as_int(t) >> 1));
    r = r * (1.5f - xh * r * r);
    r = r * (1.5f - xh * r * r);
    r = r * (1.5f - xh * r * r);
    float s = t * r;
    float c = x - s;
    return fminf(fmaxf(c, 0.0f), 1.0f);
}

static __device__ __forceinline__ float to_tf32(float x) {
    unsigned u;
    asm("cvt.rna.tf32.f32 %0, %1;" : "=r"(u) : "f"(x));
    return __uint_as_float(u);
}

#define AP 132            // smem pitch (floats), conflict-free fragment LDS
#define SP 144            // fp8 stage pitch (bytes), 16B-aligned rows
#define BUILD_SMEM (2 * 128 * AP * 4)

// tf32 tensor-core build, FUSED with fragment repack: one block = one
// 128x128 upper-triangle tile (I,J). Epilogue converts to fp8 in smem, then
// writes the m16n8k32 A-FRAGMENT layout directly for the tile AND (offdiag)
// its transposed mirror. No normal-layout array, no separate repack pass.
__global__ void __launch_bounds__(256, 1)
build_tf32_kernel(const float* __restrict__ emb) {
    extern __shared__ float dynb[];
    float* Asm = dynb;                 // [128][AP]
    float* Bsm = dynb + 128 * AP;

    int t = blockIdx.x, I = 0;
    while (t >= 16 - I) { t -= 16 - I; I++; }
    int J = I + t;
    int b = blockIdx.y;
    bool offdiag = (J != I);

    int tid = threadIdx.x;
    int w = tid >> 5, lane = tid & 31;
    int gid = lane >> 2, tig = lane & 3;

    const float* EI = emb + ((size_t)b * NN + I * 128) * DD;
    const float* EJ = emb + ((size_t)b * NN + J * 128) * DD;

    // stage both 128x128 tiles, tf32-rounded; negate time component on A side
    #pragma unroll
    for (int i = 0; i < 16; i++) {
        int idx = tid + i * 256;
        int r = idx >> 5, q = idx & 31;
        float4 v = *(const float4*)(EI + (size_t)r * DD + q * 4);
        if (q == 0) v.x = -v.x;
        float* d = &Asm[r * AP + q * 4];
        d[0] = to_tf32(v.x); d[1] = to_tf32(v.y);
        d[2] = to_tf32(v.z); d[3] = to_tf32(v.w);
        float4 u = *(const float4*)(EJ + (size_t)r * DD + q * 4);
        float* e = &Bsm[r * AP + q * 4];
        e[0] = to_tf32(u.x); e[1] = to_tf32(u.y);
        e[2] = to_tf32(u.z); e[3] = to_tf32(u.w);
    }
    __syncthreads();

    float acc[16][4];
    #pragma unroll
    for (int nt = 0; nt < 16; nt++) {
        acc[nt][0] = 0.f; acc[nt][1] = 0.f; acc[nt][2] = 0.f; acc[nt][3] = 0.f;
    }

    int mrow = (w << 4) + gid;         // warp's m-tile rows: mrow, mrow+8
    #pragma unroll
    for (int k0 = 0; k0 < 128; k0 += 8) {
        const float* Ab = &Asm[mrow * AP + k0 + tig];
        unsigned a0 = __float_as_uint(Ab[0]);
        unsigned a1 = __float_as_uint(Ab[8 * AP]);
        unsigned a2 = __float_as_uint(Ab[4]);
        unsigned a3 = __float_as_uint(Ab[8 * AP + 4]);
        #pragma unroll
        for (int nt = 0; nt < 16; nt++) {
            const float* Bb = &Bsm[(nt * 8 + gid) * AP + k0 + tig];
            unsigned b0 = __float_as_uint(Bb[0]);
            unsigned b1 = __float_as_uint(Bb[4]);
            asm volatile(
                "mma.sync.aligned.m16n8k8.row.col.f32.tf32.tf32.f32 "
                "{%0,%1,%2,%3}, {%4,%5,%6,%7}, {%8,%9}, {%0,%1,%2,%3};"
                : "+f"(acc[nt][0]), "+f"(acc[nt][1]), "+f"(acc[nt][2]), "+f"(acc[nt][3])
                : "r"(a0), "r"(a1), "r"(a2), "r"(a3), "r"(b0), "r"(b1));
        }
    }
    __syncthreads();

    // fp8 stage (aliases Asm region): stg[r][c] = C[I*128+r][J*128+c]
    unsigned char* stg = (unsigned char*)dynb;
    #pragma unroll
    for (int nt = 0; nt < 16; nt++) {
        float c0 = coupling_from_lz(acc[nt][0]);   // (mrow,   2tig)
        float c1 = coupling_from_lz(acc[nt][1]);   // (mrow,   2tig+1)
        float c2 = coupling_from_lz(acc[nt][2]);   // (mrow+8, 2tig)
        float c3 = coupling_from_lz(acc[nt][3]);   // (mrow+8, 2tig+1)
        unsigned short p01 = (unsigned short)__nv_cvt_float2_to_fp8x2(
            make_float2(c0, c1), __NV_SATFINITE, __NV_E4M3);
        unsigned short p23 = (unsigned short)__nv_cvt_float2_to_fp8x2(
            make_float2(c2, c3), __NV_SATFINITE, __NV_E4M3);
        int col = nt * 8 + tig * 2;
        *(unsigned short*)(stg + mrow * SP + col)       = p01;
        *(unsigned short*)(stg + (mrow + 8) * SP + col) = p23;
    }
    __syncthreads();

    // Fragment-layout write, normal orientation (m-rows = I, k-cols = J):
    // subtile (mtl 0..7, ktl 0..3); fragment lane ln (g=ln>>2, ti=ln&3) takes
    //   {A[g][ti*4..], A[g+8][ti*4..], A[g][16+ti*4..], A[g+8][16+ti*4..]}
    #pragma unroll
    for (int s = 0; s < 4; s++) {
        int idx = tid + s * 256;          // 0..1023 = 32 subtiles x 32 lanes
        int sub = idx >> 5, ln = idx & 31;
        int mtl = sub >> 2, ktl = sub & 3;
        int g = ln >> 2, ti = ln & 3;
        const unsigned char* base = stg + (mtl * 16 + g) * SP + ktl * 32 + ti * 4;
        uint4 o;
        o.x = *(const unsigned*)(base);
        o.y = *(const unsigned*)(base + 8 * SP);
        o.z = *(const unsigned*)(base + 16);
        o.w = *(const unsigned*)(base + 8 * SP + 16);
        size_t toff = (((size_t)(b * 128 + I * 8 + mtl)) * 64 + J * 4 + ktl) * 512
                    + (size_t)ln * 16;
        *(uint4*)(d_Cf + toff) = o;
    }

    // Mirror orientation (m-rows = J, k-cols = I): T[r][c] = stg[c][r]
    if (offdiag) {
        #pragma unroll
        for (int s = 0; s < 4; s++) {
            int idx = tid + s * 256;
            int sub = idx >> 5, ln = idx & 31;
            int mtl = sub >> 2, ktl = sub & 3;
            int g = ln >> 2, ti = ln & 3;
            int mr = mtl * 16 + g;
            int kc = ktl * 32 + ti * 4;
            unsigned wds[4];
            #pragma unroll
            for (int half = 0; half < 2; half++) {      // k halves +0 / +16
                #pragma unroll
                for (int rr = 0; rr < 2; rr++) {        // rows mr / mr+8
                    int r = mr + rr * 8;
                    int c = kc + half * 16;
                    unsigned x0 = stg[(c + 0) * SP + r];
                    unsigned x1 = stg[(c + 1) * SP + r];
                    unsigned x2 = stg[(c + 2) * SP + r];
                    unsigned x3 = stg[(c + 3) * SP + r];
                    wds[half * 2 + rr] = x0 | (x1 << 8) | (x2 << 16) | (x3 << 24);
                }
            }
            uint4 o = make_uint4(wds[0], wds[1], wds[2], wds[3]);
            size_t toff = (((size_t)(b * 128 + J * 8 + mtl)) * 64 + I * 4 + ktl) * 512
                        + (size_t)ln * 16;
            *(uint4*)(d_Cf + toff) = o;
        }
    }
}

__global__ void init_trig_kernel(const float* __restrict__ th) {
    int i = blockIdx.x * 256 + threadIdx.x;
    float s, c;
    sincosf(th[i], &s, &c);
    d_cos8[0][i] = (unsigned char)__nv_cvt_float_to_fp8(c, __NV_SATFINITE, __NV_E4M3);
    d_sin8[0][i] = (unsigned char)__nv_cvt_float_to_fp8(s, __NV_SATFINITE, __NV_E4M3);
}

// PERSISTENT step kernel, smem-pinned C: 128 co-resident blocks (1/SM).
// 27 of each warp's 32 k-slabs (216KB) are staged into shared memory ONCE;
// only 5 slabs/warp stream from L2 per step. Steps become LSU-port-bound
// (~1.2us) instead of LTS-cap-bound (~3us+).
#define S_SLABS 27
#define G_SLABS 5
#define SMEM_STEPS (16 * S_SLABS * 512 + 4096 + 2048)

__global__ void __launch_bounds__(512, 1)
steps_kernel(const float* __restrict__ th_in,
             float* __restrict__ th_out,
             const float* __restrict__ omega) {
    extern __shared__ __align__(16) unsigned char dyn[];
    unsigned char* scC = dyn;                                 // 16*27*512
    unsigned* shCos = (unsigned*)(dyn + 16 * S_SLABS * 512);  // 512 words
    unsigned* shSin = shCos + 512;
    float* shPC = (float*)(shSin + 512);                      // [2][128]
    float* shPS = shPC + 256;

    int rg = blockIdx.x, b = blockIdx.y;
    int tid = threadIdx.x;
    int w = tid >> 5, lane = tid & 31;
    int gid = lane >> 2, tig = lane & 3;
    int mtl = w & 7, kq = w >> 3;

    int mt = rg * 8 + mtl;
    const uint4* Af = (const uint4*)(d_Cf
        + (((size_t)(b * 128 + mt)) * 64 + kq * 32) * 512) + lane;
    int bbase = kq * 256 + tig;

    // one-time stage: 27 slabs/warp into smem
    unsigned char* myC = scC + (size_t)(w * S_SLABS) * 512 + lane * 16;
    #pragma unroll
    for (int i = 0; i < S_SLABS; i++)
        *(uint4*)(myC + i * 512) = Af[i * 32];

    // global-slab register pipeline (step-invariant addresses, wraps)
    uint4 g[G_SLABS];
    #pragma unroll
    for (int i = 0; i < G_SLABS; i++) g[i] = Af[(S_SLABS + i) * 32];

    // register-resident oscillator state (tid < 128)
    int gi = b * NN + rg * 128 + tid;
    float th = 0.f, om = 0.f, sn = 0.f, cn = 0.f;
    if (tid < 128) {
        th = th_in[gi];
        om = omega[rg * 128 + tid];
        sincosf(th, &sn, &cn);
    }

    for (int k = 0; k < 16; k++) {
        if (k > 0) {
            if (tid == 0) {
                unsigned target = 16u * (unsigned)k;
                unsigned v;
                do {
                    asm volatile("ld.acquire.gpu.global.u32 %0, [%1];"
                                 : "=r"(v) : "l"(&d_barStep[b]) : "memory");
                } while (v < target);
            }
            __syncthreads();
        }

        // stage this batch's trig (buffer k&1)
        {
            const unsigned* gc = (const unsigned*)(d_cos8[k & 1] + (size_t)b * NN);
            const unsigned* gs = (const unsigned*)(d_sin8[k & 1] + (size_t)b * NN);
            shCos[tid] = __ldcg(gc + tid);
            shSin[tid] = __ldcg(gs + tid);
        }
        __syncthreads();

        const unsigned* bp = (gid == 1) ? shSin : shCos;

        // dual accumulator sets break the MMA RAW chain
        float a0 = 0.f, a1 = 0.f, a2 = 0.f, a3 = 0.f;
        float e0 = 0.f, e1 = 0.f, e2 = 0.f, e3 = 0.f;

        #pragma unroll
        for (int it = 0; it < S_SLABS; it++) {
            uint4 f = *(const uint4*)(myC + it * 512);
            unsigned b0 = bp[bbase + it * 8];
            unsigned b1 = bp[bbase + it * 8 + 4];
            if (it & 1)
                asm volatile(
                    "mma.sync.aligned.m16n8k32.row.col.f32.e4m3.e4m3.f32 "
                    "{%0,%1,%2,%3}, {%4,%5,%6,%7}, {%8,%9}, {%0,%1,%2,%3};"
                    : "+f"(e0), "+f"(e1), "+f"(e2), "+f"(e3)
                    : "r"(f.x), "r"(f.y), "r"(f.z), "r"(f.w), "r"(b0), "r"(b1));
            else
                asm volatile(
                    "mma.sync.aligned.m16n8k32.row.col.f32.e4m3.e4m3.f32 "
                    "{%0,%1,%2,%3}, {%4,%5,%6,%7}, {%8,%9}, {%0,%1,%2,%3};"
                    : "+f"(a0), "+f"(a1), "+f"(a2), "+f"(a3)
                    : "r"(f.x), "r"(f.y), "r"(f.z), "r"(f.w), "r"(b0), "r"(b1));
        }
        #pragma unroll
        for (int j = 0; j < G_SLABS; j++) {
            uint4 f = g[j];
            g[j] = Af[(S_SLABS + j) * 32];        // prefetch for next step
            int it = S_SLABS + j;
            unsigned b0 = bp[bbase + it * 8];
            unsigned b1 = bp[bbase + it * 8 + 4];
            if (it & 1)
                asm volatile(
                    "mma.sync.aligned.m16n8k32.row.col.f32.e4m3.e4m3.f32 "
                    "{%0,%1,%2,%3}, {%4,%5,%6,%7}, {%8,%9}, {%0,%1,%2,%3};"
                    : "+f"(e0), "+f"(e1), "+f"(e2), "+f"(e3)
                    : "r"(f.x), "r"(f.y), "r"(f.z), "r"(f.w), "r"(b0), "r"(b1));
            else
                asm volatile(
                    "mma.sync.aligned.m16n8k32.row.col.f32.e4m3.e4m3.f32 "
                    "{%0,%1,%2,%3}, {%4,%5,%6,%7}, {%8,%9}, {%0,%1,%2,%3};"
                    : "+f"(a0), "+f"(a1), "+f"(a2), "+f"(a3)
                    : "r"(f.x), "r"(f.y), "r"(f.z), "r"(f.w), "r"(b0), "r"(b1));
        }

        float d0 = a0 + e0, d1 = a1 + e1, d2 = a2 + e2, d3 = a3 + e3;

        if (tig == 0) {
            int lr = mtl * 16 + gid;
            shPC[kq * 128 + lr]     = d0;
            shPS[kq * 128 + lr]     = d1;
            shPC[kq * 128 + lr + 8] = d2;
            shPS[kq * 128 + lr + 8] = d3;
        }
        __syncthreads();

        if (tid < 128) {
            float yc = shPC[tid] + shPC[128 + tid];   // fixed order -> deterministic
            float ys = shPS[tid] + shPS[128 + tid];
            float csum = sn * yc - cn * ys;
            float dth = om + (1.0f / NN) * csum;
            th = fmodf(th + 0.1f * dth, TWO_PI_F);
            sincosf(th, &sn, &cn);
            if (k < 15) {
                d_cos8[(k + 1) & 1][gi] =
                    (unsigned char)__nv_cvt_float_to_fp8(cn, __NV_SATFINITE, __NV_E4M3);
                d_sin8[(k + 1) & 1][gi] =
                    (unsigned char)__nv_cvt_float_to_fp8(sn, __NV_SATFINITE, __NV_E4M3);
                __threadfence();                       // release trig writes
            } else {
                th_out[gi] = th;
            }
        }
        __syncthreads();
        if (k < 15 && tid == 0)
            asm volatile("red.release.gpu.global.add.u32 [%0], %1;"
                         :: "l"(&d_barStep[b]), "r"(1u) : "memory");
    }

    // exit: last block resets counters so every graph replay starts clean
    __syncthreads();
    if (tid == 0) {
        int old = atomicAdd(&d_barExit, 1);
        if (old == 127) {
            #pragma unroll
            for (int i = 0; i < BB; i++) atomicExch(&d_barStep[i], 0u);
            atomicExch(&d_barExit, 0);
        }
    }
}

extern "C" void kernel_launch(void* const* d_in, const int* in_sizes, int n_in,
                              void* d_out, int out_size) {
    const float* initial = (const float*)d_in[0];   // (B,N)
    const float* emb     = (const float*)d_in[1];   // (B,N,D)
    const float* omega   = (const float*)d_in[2];   // (N,)
    float* out = (float*)d_out;                     // (B,N)

    cudaFuncSetAttribute(build_tf32_kernel,
                         cudaFuncAttributeMaxDynamicSharedMemorySize, BUILD_SMEM);
    cudaFuncSetAttribute(steps_kernel,
                         cudaFuncAttributeMaxDynamicSharedMemorySize, SMEM_STEPS);

    dim3 bgrid(136, BB);                            // upper-triangle 128-tiles
    build_tf32_kernel<<<bgrid, 256, BUILD_SMEM>>>(emb);

    init_trig_kernel<<<BB * NN / 256, 256>>>(initial);

    dim3 sgrid(16, BB);                             // 128 blocks, all co-resident
    steps_kernel<<<sgrid, 512, SMEM_STEPS>>>(initial, out, omega);
}

// round 14
// speedup vs baseline: 1.9391x; 1.0265x over previous
#include <cuda_runtime.h>
#include <cuda_fp16.h>
#include <cuda_fp8.h>
#include <math.h>

#define BB 8
#define NN 2048
#define DD 128
#define TWO_PI_F 6.283185307179586f

// Static device scratch (no allocations allowed).
__device__ unsigned char d_Cf[(size_t)BB * NN * NN];  // coupling e4m3, m16n8k32 A-fragment layout
__device__ unsigned char d_cos8[2][BB * NN];          // ping-pong fp8 cos(theta)
__device__ unsigned char d_sin8[2][BB * NN];          // ping-pong fp8 sin(theta)
__device__ unsigned d_barStep[BB];                    // per-batch step barriers (BSS=0)
__device__ int d_barExit;                             // exit counter for reset

// coupling ≈ x - sqrt(x^2-1), x = max(-lz, 1+1e-7)
__device__ __forceinline__ float coupling_from_lz(float lz) {
    float x = fmaxf(-lz, 1.0f + 1e-7f);
    float t = (x - 1.0f) * (x + 1.0f);
    float xh = 0.5f * t;
    float r = __int_as_float(0x5f375a86 - (__float_as_int(t) >> 1));
    r = r * (1.5f - xh * r * r);
    r = r * (1.5f - xh * r * r);
    r = r * (1.5f - xh * r * r);
    float s = t * r;
    float c = x - s;
    return fminf(fmaxf(c, 0.0f), 1.0f);
}

static __device__ __forceinline__ float to_tf32(float x) {
    unsigned u;
    asm("cvt.rna.tf32.f32 %0, %1;" : "=r"(u) : "f"(x));
    return __uint_as_float(u);
}

#define AP 132            // smem pitch (floats), conflict-free fragment LDS
#define SP 144            // fp8 stage pitch (bytes), 16B-aligned rows
#define BUILD_SMEM (2 * 128 * AP * 4)

// tf32 tensor-core build, fused with fragment repack. 512 threads/block:
// 16 warps = 8 m-tiles x 2 n-halves (acc 32 regs/thread) -> 2x pipe feed vs
// the 256-thread version. One block = one 128x128 upper-triangle tile (I,J).
__global__ void __launch_bounds__(512, 1)
build_tf32_kernel(const float* __restrict__ emb) {
    extern __shared__ float dynb[];
    float* Asm = dynb;                 // [128][AP]
    float* Bsm = dynb + 128 * AP;

    int t = blockIdx.x, I = 0;
    while (t >= 16 - I) { t -= 16 - I; I++; }
    int J = I + t;
    int b = blockIdx.y;
    bool offdiag = (J != I);

    int tid = threadIdx.x;
    int w = tid >> 5, lane = tid & 31;
    int gid = lane >> 2, tig = lane & 3;
    int wr = w & 7, wc = w >> 3;       // m-tile 0..7, n-half 0..1

    const float* EI = emb + ((size_t)b * NN + I * 128) * DD;
    const float* EJ = emb + ((size_t)b * NN + J * 128) * DD;

    // stage both 128x128 tiles, tf32-rounded; negate time component on A side
    #pragma unroll
    for (int i = 0; i < 8; i++) {
        int idx = tid + i * 512;
        int r = idx >> 5, q = idx & 31;
        float4 v = *(const float4*)(EI + (size_t)r * DD + q * 4);
        if (q == 0) v.x = -v.x;
        float* d = &Asm[r * AP + q * 4];
        d[0] = to_tf32(v.x); d[1] = to_tf32(v.y);
        d[2] = to_tf32(v.z); d[3] = to_tf32(v.w);
        float4 u = *(const float4*)(EJ + (size_t)r * DD + q * 4);
        float* e = &Bsm[r * AP + q * 4];
        e[0] = to_tf32(u.x); e[1] = to_tf32(u.y);
        e[2] = to_tf32(u.z); e[3] = to_tf32(u.w);
    }
    __syncthreads();

    float acc[8][4];
    #pragma unroll
    for (int nt = 0; nt < 8; nt++) {
        acc[nt][0] = 0.f; acc[nt][1] = 0.f; acc[nt][2] = 0.f; acc[nt][3] = 0.f;
    }

    int mrow = (wr << 4) + gid;        // warp's m-tile rows: mrow, mrow+8
    #pragma unroll
    for (int k0 = 0; k0 < 128; k0 += 8) {
        const float* Ab = &Asm[mrow * AP + k0 + tig];
        unsigned a0 = __float_as_uint(Ab[0]);
        unsigned a1 = __float_as_uint(Ab[8 * AP]);
        unsigned a2 = __float_as_uint(Ab[4]);
        unsigned a3 = __float_as_uint(Ab[8 * AP + 4]);
        #pragma unroll
        for (int nt = 0; nt < 8; nt++) {
            const float* Bb = &Bsm[(wc * 64 + nt * 8 + gid) * AP + k0 + tig];
            unsigned b0 = __float_as_uint(Bb[0]);
            unsigned b1 = __float_as_uint(Bb[4]);
            asm volatile(
                "mma.sync.aligned.m16n8k8.row.col.f32.tf32.tf32.f32 "
                "{%0,%1,%2,%3}, {%4,%5,%6,%7}, {%8,%9}, {%0,%1,%2,%3};"
                : "+f"(acc[nt][0]), "+f"(acc[nt][1]), "+f"(acc[nt][2]), "+f"(acc[nt][3])
                : "r"(a0), "r"(a1), "r"(a2), "r"(a3), "r"(b0), "r"(b1));
        }
    }
    __syncthreads();

    // fp8 stage (aliases Asm region): stg[r][c] = C[I*128+r][J*128+c]
    unsigned char* stg = (unsigned char*)dynb;
    #pragma unroll
    for (int nt = 0; nt < 8; nt++) {
        float c0 = coupling_from_lz(acc[nt][0]);
        float c1 = coupling_from_lz(acc[nt][1]);
        float c2 = coupling_from_lz(acc[nt][2]);
        float c3 = coupling_from_lz(acc[nt][3]);
        unsigned short p01 = (unsigned short)__nv_cvt_float2_to_fp8x2(
            make_float2(c0, c1), __NV_SATFINITE, __NV_E4M3);
        unsigned short p23 = (unsigned short)__nv_cvt_float2_to_fp8x2(
            make_float2(c2, c3), __NV_SATFINITE, __NV_E4M3);
        int col = wc * 64 + nt * 8 + tig * 2;
        *(unsigned short*)(stg + mrow * SP + col)       = p01;
        *(unsigned short*)(stg + (mrow + 8) * SP + col) = p23;
    }
    __syncthreads();

    // Fragment-layout write, normal orientation (m-rows = I, k-cols = J)
    #pragma unroll
    for (int s = 0; s < 2; s++) {
        int idx = tid + s * 512;          // 0..1023 = 32 subtiles x 32 lanes
        int sub = idx >> 5, ln = idx & 31;
        int mtl = sub >> 2, ktl = sub & 3;
        int g = ln >> 2, ti = ln & 3;
        const unsigned char* base = stg + (mtl * 16 + g) * SP + ktl * 32 + ti * 4;
        uint4 o;
        o.x = *(const unsigned*)(base);
        o.y = *(const unsigned*)(base + 8 * SP);
        o.z = *(const unsigned*)(base + 16);
        o.w = *(const unsigned*)(base + 8 * SP + 16);
        size_t toff = (((size_t)(b * 128 + I * 8 + mtl)) * 64 + J * 4 + ktl) * 512
                    + (size_t)ln * 16;
        *(uint4*)(d_Cf + toff) = o;
    }

    // Mirror orientation (m-rows = J, k-cols = I): T[r][c] = stg[c][r]
    if (offdiag) {
        #pragma unroll
        for (int s = 0; s < 2; s++) {
            int idx = tid + s * 512;
            int sub = idx >> 5, ln = idx & 31;
            int mtl = sub >> 2, ktl = sub & 3;
            int g = ln >> 2, ti = ln & 3;
            int mr = mtl * 16 + g;
            int kc = ktl * 32 + ti * 4;
            unsigned wds[4];
            #pragma unroll
            for (int half = 0; half < 2; half++) {
                #pragma unroll
                for (int rr = 0; rr < 2; rr++) {
                    int r = mr + rr * 8;
                    int c = kc + half * 16;
                    unsigned x0 = stg[(c + 0) * SP + r];
                    unsigned x1 = stg[(c + 1) * SP + r];
                    unsigned x2 = stg[(c + 2) * SP + r];
                    unsigned x3 = stg[(c + 3) * SP + r];
                    wds[half * 2 + rr] = x0 | (x1 << 8) | (x2 << 16) | (x3 << 24);
                }
            }
            uint4 o = make_uint4(wds[0], wds[1], wds[2], wds[3]);
            size_t toff = (((size_t)(b * 128 + J * 8 + mtl)) * 64 + I * 4 + ktl) * 512
                        + (size_t)ln * 16;
            *(uint4*)(d_Cf + toff) = o;
        }
    }
}

__global__ void init_trig_kernel(const float* __restrict__ th) {
    int i = blockIdx.x * 256 + threadIdx.x;
    float s, c;
    sincosf(th[i], &s, &c);
    d_cos8[0][i] = (unsigned char)__nv_cvt_float_to_fp8(c, __NV_SATFINITE, __NV_E4M3);
    d_sin8[0][i] = (unsigned char)__nv_cvt_float_to_fp8(s, __NV_SATFINITE, __NV_E4M3);
}

// PERSISTENT step kernel, smem-pinned C. Changes vs R12/13:
//  - no per-step __threadfence (syncthreads + red.release is the release pair)
//  - trig smem stored in paired order (0,4,1,5,2,6,3,7 per slab) so both MMA
//    B-words come from ONE LDS.64
#define S_SLABS 27
#define G_SLABS 5
#define SMEM_STEPS (16 * S_SLABS * 512 + 4096 + 2048)

__global__ void __launch_bounds__(512, 1)
steps_kernel(const float* __restrict__ th_in,
             float* __restrict__ th_out,
             const float* __restrict__ omega) {
    extern __shared__ __align__(16) unsigned char dyn[];
    unsigned char* scC = dyn;                                 // 16*27*512
    unsigned* shCos = (unsigned*)(dyn + 16 * S_SLABS * 512);  // 512 words
    unsigned* shSin = shCos + 512;
    float* shPC = (float*)(shSin + 512);                      // [2][128]
    float* shPS = shPC + 256;

    int rg = blockIdx.x, b = blockIdx.y;
    int tid = threadIdx.x;
    int w = tid >> 5, lane = tid & 31;
    int gid = lane >> 2, tig = lane & 3;
    int mtl = w & 7, kq = w >> 3;

    int mt = rg * 8 + mtl;
    const uint4* Af = (const uint4*)(d_Cf
        + (((size_t)(b * 128 + mt)) * 64 + kq * 32) * 512) + lane;
    int bbase2 = kq * 256 + tig * 2;   // paired layout index

    // one-time stage: 27 slabs/warp into smem
    unsigned char* myC = scC + (size_t)(w * S_SLABS) * 512 + lane * 16;
    #pragma unroll
    for (int i = 0; i < S_SLABS; i++)
        *(uint4*)(myC + i * 512) = Af[i * 32];

    // global-slab register pipeline (step-invariant addresses, wraps)
    uint4 g[G_SLABS];
    #pragma unroll
    for (int i = 0; i < G_SLABS; i++) g[i] = Af[(S_SLABS + i) * 32];

    // register-resident oscillator state (tid < 128)
    int gi = b * NN + rg * 128 + tid;
    float th = 0.f, om = 0.f, sn = 0.f, cn = 0.f;
    if (tid < 128) {
        th = th_in[gi];
        om = omega[rg * 128 + tid];
        sincosf(th, &sn, &cn);
    }

    // permuted staging index: slab-local words reordered 0,4,1,5,2,6,3,7
    int slab = tid >> 3, pos = tid & 7;
    int permIdx = slab * 8 + ((pos & 3) << 1) + (pos >> 2);

    for (int k = 0; k < 16; k++) {
        if (k > 0) {
            if (tid == 0) {
                unsigned target = 16u * (unsigned)k;
                unsigned v;
                do {
                    asm volatile("ld.acquire.gpu.global.u32 %0, [%1];"
                                 : "=r"(v) : "l"(&d_barStep[b]) : "memory");
                } while (v < target);
            }
            __syncthreads();
        }

        // stage this batch's trig (buffer k&1), paired word order
        {
            const unsigned* gc = (const unsigned*)(d_cos8[k & 1] + (size_t)b * NN);
            const unsigned* gs = (const unsigned*)(d_sin8[k & 1] + (size_t)b * NN);
            shCos[permIdx] = __ldcg(gc + tid);
            shSin[permIdx] = __ldcg(gs + tid);
        }
        __syncthreads();

        const unsigned* bp = (gid == 1) ? shSin : shCos;

        // dual accumulator sets break the MMA RAW chain
        float a0 = 0.f, a1 = 0.f, a2 = 0.f, a3 = 0.f;
        float e0 = 0.f, e1 = 0.f, e2 = 0.f, e3 = 0.f;

        #pragma unroll
        for (int it = 0; it < S_SLABS; it++) {
            uint4 f = *(const uint4*)(myC + it * 512);
            uint2 bw = *(const uint2*)(bp + bbase2 + it * 8);
            if (it & 1)
                asm volatile(
                    "mma.sync.aligned.m16n8k32.row.col.f32.e4m3.e4m3.f32 "
                    "{%0,%1,%2,%3}, {%4,%5,%6,%7}, {%8,%9}, {%0,%1,%2,%3};"
                    : "+f"(e0), "+f"(e1), "+f"(e2), "+f"(e3)
                    : "r"(f.x), "r"(f.y), "r"(f.z), "r"(f.w), "r"(bw.x), "r"(bw.y));
            else
                asm volatile(
                    "mma.sync.aligned.m16n8k32.row.col.f32.e4m3.e4m3.f32 "
                    "{%0,%1,%2,%3}, {%4,%5,%6,%7}, {%8,%9}, {%0,%1,%2,%3};"
                    : "+f"(a0), "+f"(a1), "+f"(a2), "+f"(a3)
                    : "r"(f.x), "r"(f.y), "r"(f.z), "r"(f.w), "r"(bw.x), "r"(bw.y));
        }
        #pragma unroll
        for (int j = 0; j < G_SLABS; j++) {
            uint4 f = g[j];
            g[j] = Af[(S_SLABS + j) * 32];        // prefetch for next step
            int it = S_SLABS + j;
            uint2 bw = *(const uint2*)(bp + bbase2 + it * 8);
            if (it & 1)
                asm volatile(
                    "mma.sync.aligned.m16n8k32.row.col.f32.e4m3.e4m3.f32 "
                    "{%0,%1,%2,%3}, {%4,%5,%6,%7}, {%8,%9}, {%0,%1,%2,%3};"
                    : "+f"(e0), "+f"(e1), "+f"(e2), "+f"(e3)
                    : "r"(f.x), "r"(f.y), "r"(f.z), "r"(f.w), "r"(bw.x), "r"(bw.y));
            else
                asm volatile(
                    "mma.sync.aligned.m16n8k32.row.col.f32.e4m3.e4m3.f32 "
                    "{%0,%1,%2,%3}, {%4,%5,%6,%7}, {%8,%9}, {%0,%1,%2,%3};"
                    : "+f"(a0), "+f"(a1), "+f"(a2), "+f"(a3)
                    : "r"(f.x), "r"(f.y), "r"(f.z), "r"(f.w), "r"(bw.x), "r"(bw.y));
        }

        float d0 = a0 + e0, d1 = a1 + e1, d2 = a2 + e2, d3 = a3 + e3;

        if (tig == 0) {
            int lr = mtl * 16 + gid;
            shPC[kq * 128 + lr]     = d0;
            shPS[kq * 128 + lr]     = d1;
            shPC[kq * 128 + lr + 8] = d2;
            shPS[kq * 128 + lr + 8] = d3;
        }
        __syncthreads();

        if (tid < 128) {
            float yc = shPC[tid] + shPC[128 + tid];   // fixed order -> deterministic
            float ys = shPS[tid] + shPS[128 + tid];
            float csum = sn * yc - cn * ys;
            float dth = om + (1.0f / NN) * csum;
            th = fmodf(th + 0.1f * dth, TWO_PI_F);
            sincosf(th, &sn, &cn);
            if (k < 15) {
                d_cos8[(k + 1) & 1][gi] =
                    (unsigned char)__nv_cvt_float_to_fp8(cn, __NV_SATFINITE, __NV_E4M3);
                d_sin8[(k + 1) & 1][gi] =
                    (unsigned char)__nv_cvt_float_to_fp8(sn, __NV_SATFINITE, __NV_E4M3);
            } else {
                th_out[gi] = th;
            }
        }
        __syncthreads();   // orders trig writes before the release below
        if (k < 15 && tid == 0)
            asm volatile("red.release.gpu.global.add.u32 [%0], %1;"
                         :: "l"(&d_barStep[b]), "r"(1u) : "memory");
    }

    // exit: last block resets counters so every graph replay starts clean
    __syncthreads();
    if (tid == 0) {
        int old = atomicAdd(&d_barExit, 1);
        if (old == 127) {
            #pragma unroll
            for (int i = 0; i < BB; i++) atomicExch(&d_barStep[i], 0u);
            atomicExch(&d_barExit, 0);
        }
    }
}

extern "C" void kernel_launch(void* const* d_in, const int* in_sizes, int n_in,
                              void* d_out, int out_size) {
    const float* initial = (const float*)d_in[0];   // (B,N)
    const float* emb     = (const float*)d_in[1];   // (B,N,D)
    const float* omega   = (const float*)d_in[2];   // (N,)
    float* out = (float*)d_out;                     // (B,N)

    cudaFuncSetAttribute(build_tf32_kernel,
                         cudaFuncAttributeMaxDynamicSharedMemorySize, BUILD_SMEM);
    cudaFuncSetAttribute(steps_kernel,
                         cudaFuncAttributeMaxDynamicSharedMemorySize, SMEM_STEPS);

    dim3 bgrid(136, BB);                            // upper-triangle 128-tiles
    build_tf32_kernel<<<bgrid, 512, BUILD_SMEM>>>(emb);

    init_trig_kernel<<<BB * NN / 256, 256>>>(initial);

    dim3 sgrid(16, BB);                             // 128 blocks, all co-resident
    steps_kernel<<<sgrid, 512, SMEM_STEPS>>>(initial, out, omega);
}